// round 8
// baseline (speedup 1.0000x reference)
#include <cuda_runtime.h>
#include <cuda_fp16.h>
#include <cstdint>

// Problem constants
#define D 512
#define S 32
#define H 64
#define MROWS 128           // rows per CTA
#define THREADS 128         // 4 warps, warp = 32 rows x 64 n
#define ASTRIDE 144         // bytes per A row (64 fp16 + pad) -> conflict-free ldmatrix
#define BSTRIDE 144         // bytes per B n-row (64 fp16 k + pad)
#define BTILE (64*BSTRIDE)  // 9216 B (fp16 W tile)

// smem byte offsets
#define SM_AHI 0
#define SM_ALO (SM_AHI + MROWS*ASTRIDE)   // 18432
#define SM_B0  (SM_ALO + MROWS*ASTRIDE)   // 36864 (+buf*BTILE, double buffered)
#define SM_SKP (SM_B0 + 2*BTILE)          // 55296 (128 floats)
#define SM_TOTAL (SM_SKP + MROWS*4)       // 55808  -> 4 CTAs/SM

// W1 pre-rounded fp16, n-major: [s][n=64][k=72pad]
__device__ __half  g_Bh[S * 64 * 72];
__device__ float2  g_b1w2[S * H];
__device__ float   g_swg[S * 64];   // skip_w[col_ids]/4
__device__ float   g_extras;        // skip_b + sum(b2)

// ------------------------------------------------------------------ helpers
__device__ __forceinline__ unsigned smem_u32(const void* p) {
    return (unsigned)__cvta_generic_to_shared(p);
}

// fp16 hi/lo split of two floats, packed
__device__ __forceinline__ unsigned pack_pair(float a, float b, unsigned& lo) {
    __half ha = __float2half_rn(a), hb = __float2half_rn(b);
    __half la = __float2half_rn(a - __half2float(ha));
    __half lb = __float2half_rn(b - __half2float(hb));
    lo = ((unsigned)__half_as_ushort(lb) << 16) | (unsigned)__half_as_ushort(la);
    return ((unsigned)__half_as_ushort(hb) << 16) | (unsigned)__half_as_ushort(ha);
}

#define LDSM_X4(r0,r1,r2,r3,addr) \
    asm volatile("ldmatrix.sync.aligned.m8n8.x4.shared.b16 {%0,%1,%2,%3}, [%4];" \
        : "=r"(r0),"=r"(r1),"=r"(r2),"=r"(r3) : "r"(addr))

#define MMA_F16(d,a0,a1,a2,a3,b0,b1) \
    asm volatile("mma.sync.aligned.m16n8k16.row.col.f32.f16.f16.f32 " \
        "{%0,%1,%2,%3}, {%4,%5,%6,%7}, {%8,%9}, {%0,%1,%2,%3};" \
        : "+f"((d)[0]),"+f"((d)[1]),"+f"((d)[2]),"+f"((d)[3]) \
        : "r"(a0),"r"(a1),"r"(a2),"r"(a3),"r"(b0),"r"(b1))

#define CP16(dst, src) \
    asm volatile("cp.async.cg.shared.global [%0], [%1], 16;" :: "r"(dst), "l"(src))
#define CP_COMMIT() asm volatile("cp.async.commit_group;")
#define CP_WAIT0()  asm volatile("cp.async.wait_group 0;")

// ------------------------------------------------------------------ fused prep
__global__ void prep_all(const float* __restrict__ W1,
                         const float* __restrict__ skip_w,
                         const float* __restrict__ skip_b,
                         const float* __restrict__ b1,
                         const float* __restrict__ W2,
                         const float* __restrict__ b2,
                         const int*   __restrict__ col_ids)
{
    int idx = blockIdx.x * blockDim.x + threadIdx.x;
    if (idx < S * 64 * 72) {
        int s = idx / (64 * 72);
        int rem = idx % (64 * 72);
        int n = rem / 72;           // h index (B row, n-major)
        int k = rem % 72;           // c index
        float v = (k < 64) ? W1[(size_t)s * 4096 + (size_t)k * 64 + n] : 0.f;
        g_Bh[idx] = __float2half_rn(v);
        return;
    }
    int r = idx - S * 64 * 72;
    if (r < S * H) { g_b1w2[r] = make_float2(b1[r], W2[r]); return; }
    r -= S * H;
    if (r < S * 64) { g_swg[r] = skip_w[col_ids[r]] * 0.25f; return; }
    if (r == S * 64) {
        float e = skip_b[0];
        for (int s = 0; s < S; ++s) e += b2[s];
        g_extras = e;
    }
}

// ------------------------------------------------------------------ main
__global__ void __launch_bounds__(THREADS, 4)
hybrid_main(const float* __restrict__ x,
            const int*   __restrict__ col_ids,
            float* __restrict__ out)
{
    extern __shared__ char smem[];
    const unsigned sbase = smem_u32(smem);
    const int tid  = threadIdx.x;
    const int lane = tid & 31;
    const int wid  = tid >> 5;          // 0..3
    const int rowbase = blockIdx.x * MROWS;

    // A ldmatrix lane address (mt tile offset = 16*ASTRIDE = 2304)
    const int a_row = wid * 32 + ((lane >> 3) & 1) * 8 + (lane & 7);
    const unsigned a_hi = sbase + SM_AHI + a_row * ASTRIDE + (lane >> 4) * 16;
    const unsigned a_lo = a_hi + (SM_ALO - SM_AHI);

    // B ldmatrix (non-trans x4, n-major rows):
    // group g=lane>>3: n = (g>>1)*8 + (lane&7), koff = (g&1)*16
    const int bg = lane >> 3;
    const unsigned b_base = sbase + SM_B0
        + (((bg >> 1) * 8) + (lane & 7)) * BSTRIDE + (bg & 1) * 16;

    // gather identity: thread = full row
    const float* xrow = x + (size_t)(rowbase + tid) * D;
    char* dst_hi = smem + SM_AHI + tid * ASTRIDE;
    char* dst_lo = dst_hi + (SM_ALO - SM_AHI);

    // ---------------- prologue: cp.async B(0) ----------------
    {
        const char* gb = reinterpret_cast<const char*>(g_Bh);
        const unsigned db = sbase + SM_B0;
        #pragma unroll
        for (int i = 0; i < 5; ++i) {
            int j = tid + i * THREADS;
            if (j < BTILE / 16) CP16(db + j * 16, gb + j * 16);
        }
        CP_COMMIT();
    }

    float rowacc[2][2] = {{0.f, 0.f}, {0.f, 0.f}};
    float skipacc = 0.f;
    int cid0 = col_ids[0];
    int cid1 = col_ids[32];

    for (int s = 0; s < S; ++s) {
        const int buf = s & 1;
        __syncthreads();   // A(s-1) fully consumed by all warps

        // ---- gather full row (2 halves) + fp16 hi/lo convert + fp32 skip dot
        {
            const float4* sw4 = reinterpret_cast<const float4*>(g_swg + s * 64);
            const float4* src0 = reinterpret_cast<const float4*>(xrow + cid0);
            const float4* src1 = reinterpret_cast<const float4*>(xrow + cid1);
            float sk = 0.f;
            #pragma unroll
            for (int h = 0; h < 2; ++h) {
                const float4* src = h ? src1 : src0;
                #pragma unroll
                for (int i = 0; i < 4; ++i) {
                    float4 fa = src[2*i], fb = src[2*i+1];
                    float4 wa = sw4[h*8 + 2*i], wb = sw4[h*8 + 2*i + 1];
                    sk += fa.x*wa.x + fa.y*wa.y + fa.z*wa.z + fa.w*wa.w;
                    sk += fb.x*wb.x + fb.y*wb.y + fb.z*wb.z + fb.w*wb.w;
                    uint4 hv, lv;
                    hv.x = pack_pair(fa.x, fa.y, lv.x);
                    hv.y = pack_pair(fa.z, fa.w, lv.y);
                    hv.z = pack_pair(fb.x, fb.y, lv.z);
                    hv.w = pack_pair(fb.z, fb.w, lv.w);
                    *reinterpret_cast<uint4*>(dst_hi + h * 64 + i * 16) = hv;
                    *reinterpret_cast<uint4*>(dst_lo + h * 64 + i * 16) = lv;
                }
            }
            skipacc += sk;
        }

        CP_WAIT0();        // B(s) landed (only outstanding group)
        __syncthreads();   // A(s) + B(s) visible to all

        // ---- prefetch B(s+1) into other buffer; advance col bases
        if (s + 1 < S) {
            const char* gb = reinterpret_cast<const char*>(g_Bh) + (size_t)(s + 1) * BTILE;
            const unsigned db = sbase + SM_B0 + (buf ^ 1) * BTILE;
            #pragma unroll
            for (int i = 0; i < 5; ++i) {
                int j = tid + i * THREADS;
                if (j < BTILE / 16) CP16(db + j * 16, gb + j * 16);
            }
            CP_COMMIT();
            cid0 = col_ids[(s + 1) * 64];
            cid1 = col_ids[(s + 1) * 64 + 32];
        }

        // ---- 2-term split MMA: D[32x64] per warp
        float d[2][8][4];
        #pragma unroll
        for (int mt = 0; mt < 2; ++mt)
            #pragma unroll
            for (int nt = 0; nt < 8; ++nt)
                { d[mt][nt][0]=0.f; d[mt][nt][1]=0.f; d[mt][nt][2]=0.f; d[mt][nt][3]=0.f; }

        const unsigned bseg = b_base + buf * BTILE;
        #pragma unroll
        for (int kk = 0; kk < 4; ++kk) {
            unsigned ah[2][4], al[2][4];
            #pragma unroll
            for (int mt = 0; mt < 2; ++mt) {
                LDSM_X4(ah[mt][0], ah[mt][1], ah[mt][2], ah[mt][3], a_hi + mt * 2304 + kk * 32);
                LDSM_X4(al[mt][0], al[mt][1], al[mt][2], al[mt][3], a_lo + mt * 2304 + kk * 32);
            }
            #pragma unroll
            for (int ntp = 0; ntp < 4; ++ntp) {
                unsigned bh0, bh1, bh2, bh3;
                LDSM_X4(bh0, bh1, bh2, bh3, bseg + ntp * 2304 + kk * 32);
                #pragma unroll
                for (int mt = 0; mt < 2; ++mt) {
                    MMA_F16(d[mt][2*ntp],   ah[mt][0],ah[mt][1],ah[mt][2],ah[mt][3], bh0, bh1);
                    MMA_F16(d[mt][2*ntp],   al[mt][0],al[mt][1],al[mt][2],al[mt][3], bh0, bh1);
                    MMA_F16(d[mt][2*ntp+1], ah[mt][0],ah[mt][1],ah[mt][2],ah[mt][3], bh2, bh3);
                    MMA_F16(d[mt][2*ntp+1], al[mt][0],al[mt][1],al[mt][2],al[mt][3], bh2, bh3);
                }
            }
        }

        // ---- epilogue: relu(d+b1).W2 (fp32 params, L1-resident), quad reduce
        {
            const float2* bw = g_b1w2 + s * H;
            const int cbase = 2 * (lane & 3);
            #pragma unroll
            for (int mt = 0; mt < 2; ++mt) {
                float p0 = 0.f, p1 = 0.f;
                #pragma unroll
                for (int nt = 0; nt < 8; ++nt) {
                    const float2 bw0 = bw[nt * 8 + cbase];
                    const float2 bw1 = bw[nt * 8 + cbase + 1];
                    p0 += fmaxf(d[mt][nt][0] + bw0.x, 0.f) * bw0.y;
                    p0 += fmaxf(d[mt][nt][1] + bw1.x, 0.f) * bw1.y;
                    p1 += fmaxf(d[mt][nt][2] + bw0.x, 0.f) * bw0.y;
                    p1 += fmaxf(d[mt][nt][3] + bw1.x, 0.f) * bw1.y;
                }
                p0 += __shfl_xor_sync(0xffffffffu, p0, 1);
                p0 += __shfl_xor_sync(0xffffffffu, p0, 2);
                p1 += __shfl_xor_sync(0xffffffffu, p1, 1);
                p1 += __shfl_xor_sync(0xffffffffu, p1, 2);
                rowacc[mt][0] += p0;
                rowacc[mt][1] += p1;
            }
        }
    }

    // ---- finalize: publish skip dots, then write
    {
        float* skp = reinterpret_cast<float*>(smem + SM_SKP);
        skp[tid] = skipacc;
    }
    __syncthreads();

    if ((lane & 3) == 0) {
        const float* skp = reinterpret_cast<const float*>(smem + SM_SKP);
        const float extras = g_extras;
        #pragma unroll
        for (int mt = 0; mt < 2; ++mt) {
            const int lr = wid * 32 + mt * 16 + (lane >> 2);
            float v0 = rowacc[mt][0] + extras + skp[lr];
            float v1 = rowacc[mt][1] + extras + skp[lr + 8];
            out[rowbase + lr]     = fminf(fmaxf(v0, -20.0f), 20.0f);
            out[rowbase + lr + 8] = fminf(fmaxf(v1, -20.0f), 20.0f);
        }
    }
}

// ------------------------------------------------------------------ launch
extern "C" void kernel_launch(void* const* d_in, const int* in_sizes, int n_in,
                              void* d_out, int out_size)
{
    const float* x       = (const float*)d_in[0];
    const float* skip_w  = (const float*)d_in[1];
    const float* skip_b  = (const float*)d_in[2];
    const float* W1      = (const float*)d_in[3];
    const float* b1      = (const float*)d_in[4];
    const float* W2      = (const float*)d_in[5];
    const float* b2      = (const float*)d_in[6];
    const int*   col_ids = (const int*)  d_in[7];
    float* out = (float*)d_out;

    static bool attr_set = false;
    if (!attr_set) {
        cudaFuncSetAttribute(hybrid_main,
                             cudaFuncAttributeMaxDynamicSharedMemorySize, SM_TOTAL);
        attr_set = true;
    }

    const int prep_items = S * 64 * 72 + S * H + S * 64 + 1;
    prep_all<<<(prep_items + 255) / 256, 256>>>(W1, skip_w, skip_b, b1, W2, b2, col_ids);

    const int nrows = in_sizes[0] / D;   // 65536
    const int grid  = nrows / MROWS;     // 512
    hybrid_main<<<grid, THREADS, SM_TOTAL>>>(x, col_ids, out);
}

// round 9
// speedup vs baseline: 1.6486x; 1.6486x over previous
#include <cuda_runtime.h>
#include <cuda_fp16.h>
#include <cstdint>

// Problem constants
#define D 512
#define S 32
#define H 64
#define MROWS 256           // rows per CTA
#define THREADS 256         // 8 warps, warp = 32 rows x 64 n (MMA phase)
#define ASTRIDE 144         // bytes per A row (64 fp16 + pad) -> conflict-free ldmatrix
#define BSTRIDE 144         // bytes per B n-row (64 fp16 k + pad)
#define BTILE (64*BSTRIDE)  // 9216 B (fp16 W tile)

// smem byte offsets
#define SM_AHI 0
#define SM_ALO (SM_AHI + MROWS*ASTRIDE)   // 36864
#define SM_B0  (SM_ALO + MROWS*ASTRIDE)   // 73728 (+buf*BTILE, double buffered)
#define SM_SKP (SM_B0 + 2*BTILE)          // 92160 (256 floats)
#define SM_TOTAL (SM_SKP + MROWS*4)       // 93184  -> 2 CTAs/SM

// W1 pre-rounded fp16, n-major: [s][n=64][k=72pad]
__device__ __half  g_Bh[S * 64 * 72];
__device__ float2  g_b1w2[S * H];
__device__ float   g_swg[S * 64];   // skip_w[col_ids]/4
__device__ float   g_extras;        // skip_b + sum(b2)

// ------------------------------------------------------------------ helpers
__device__ __forceinline__ unsigned smem_u32(const void* p) {
    return (unsigned)__cvta_generic_to_shared(p);
}

// fp16 hi/lo split of two floats, packed
__device__ __forceinline__ unsigned pack_pair(float a, float b, unsigned& lo) {
    __half ha = __float2half_rn(a), hb = __float2half_rn(b);
    __half la = __float2half_rn(a - __half2float(ha));
    __half lb = __float2half_rn(b - __half2float(hb));
    lo = ((unsigned)__half_as_ushort(lb) << 16) | (unsigned)__half_as_ushort(la);
    return ((unsigned)__half_as_ushort(hb) << 16) | (unsigned)__half_as_ushort(ha);
}

#define LDSM_X4(r0,r1,r2,r3,addr) \
    asm volatile("ldmatrix.sync.aligned.m8n8.x4.shared.b16 {%0,%1,%2,%3}, [%4];" \
        : "=r"(r0),"=r"(r1),"=r"(r2),"=r"(r3) : "r"(addr))

#define MMA_F16(d,a0,a1,a2,a3,b0,b1) \
    asm volatile("mma.sync.aligned.m16n8k16.row.col.f32.f16.f16.f32 " \
        "{%0,%1,%2,%3}, {%4,%5,%6,%7}, {%8,%9}, {%0,%1,%2,%3};" \
        : "+f"((d)[0]),"+f"((d)[1]),"+f"((d)[2]),"+f"((d)[3]) \
        : "r"(a0),"r"(a1),"r"(a2),"r"(a3),"r"(b0),"r"(b1))

#define CP16(dst, src) \
    asm volatile("cp.async.cg.shared.global [%0], [%1], 16;" :: "r"(dst), "l"(src))
#define CP_COMMIT() asm volatile("cp.async.commit_group;")
#define CP_WAIT0()  asm volatile("cp.async.wait_group 0;")

// ------------------------------------------------------------------ fused prep
__global__ void prep_all(const float* __restrict__ W1,
                         const float* __restrict__ skip_w,
                         const float* __restrict__ skip_b,
                         const float* __restrict__ b1,
                         const float* __restrict__ W2,
                         const float* __restrict__ b2,
                         const int*   __restrict__ col_ids)
{
    int idx = blockIdx.x * blockDim.x + threadIdx.x;
    if (idx < S * 64 * 72) {
        int s = idx / (64 * 72);
        int rem = idx % (64 * 72);
        int n = rem / 72;           // h index (B row, n-major)
        int k = rem % 72;           // c index
        float v = (k < 64) ? W1[(size_t)s * 4096 + (size_t)k * 64 + n] : 0.f;
        g_Bh[idx] = __float2half_rn(v);
        return;
    }
    int r = idx - S * 64 * 72;
    if (r < S * H) { g_b1w2[r] = make_float2(b1[r], W2[r]); return; }
    r -= S * H;
    if (r < S * 64) { g_swg[r] = skip_w[col_ids[r]] * 0.25f; return; }
    if (r == S * 64) {
        float e = skip_b[0];
        for (int s = 0; s < S; ++s) e += b2[s];
        g_extras = e;
    }
}

// ------------------------------------------------------------------ main
__global__ void __launch_bounds__(THREADS, 2)
hybrid_main(const float* __restrict__ x,
            const int*   __restrict__ col_ids,
            float* __restrict__ out)
{
    extern __shared__ char smem[];
    const unsigned sbase = smem_u32(smem);
    const int tid  = threadIdx.x;
    const int lane = tid & 31;
    const int wid  = tid >> 5;
    const int rowbase = blockIdx.x * MROWS;

    // A ldmatrix lane address (mt tile offset = 16*ASTRIDE = 2304)
    const int a_row = wid * 32 + ((lane >> 3) & 1) * 8 + (lane & 7);
    const unsigned a_hi = sbase + SM_AHI + a_row * ASTRIDE + (lane >> 4) * 16;
    const unsigned a_lo = a_hi + (SM_ALO - SM_AHI);

    // B ldmatrix (non-trans x4, n-major rows):
    // group g=lane>>3: n = (g>>1)*8 + (lane&7), koff = (g&1)*16
    const int bg = lane >> 3;
    const unsigned b_base = sbase + SM_B0
        + (((bg >> 1) * 8) + (lane & 7)) * BSTRIDE + (bg & 1) * 16;

    // gather identity: warp covers 8 rows x 4 lanes (32B each, coalesced)
    const int gr0 = wid * 8 + (lane >> 2);   // row within each 64-row block
    const int gc2 = lane & 3;                // 32B unit within the 128B half
    const float* xb = x + (size_t)rowbase * D + gc2 * 8;

    // ---------------- prologue: cp.async B(0) ----------------
    {
        const char* gb = reinterpret_cast<const char*>(g_Bh);
        const unsigned db = sbase + SM_B0;
        #pragma unroll
        for (int i = 0; i < 3; ++i) {
            int j = tid + i * THREADS;
            if (j < BTILE / 16) CP16(db + j * 16, gb + j * 16);
        }
        CP_COMMIT();
    }

    float rowacc[2][2] = {{0.f, 0.f}, {0.f, 0.f}};
    float skacc[4] = {0.f, 0.f, 0.f, 0.f};
    int cid0 = col_ids[0];
    int cid1 = col_ids[32];

    for (int s = 0; s < S; ++s) {
        const int buf = s & 1;
        __syncthreads();   // A(s-1) fully consumed by all warps

        // ---- coalesced gather + fp16 hi/lo convert + fp32 skip partials
        {
            const float* swg_s = g_swg + s * 64 + gc2 * 8;
            #pragma unroll
            for (int j = 0; j < 4; ++j) {
                const int row = j * 64 + gr0;
                const float* xr = xb + (size_t)row * D;
                char* dh = smem + SM_AHI + row * ASTRIDE + gc2 * 16;
                char* dl = dh + (SM_ALO - SM_AHI);
                float sk = 0.f;
                #pragma unroll
                for (int h = 0; h < 2; ++h) {
                    const float* src = xr + (h ? cid1 : cid0);
                    float4 fa = *reinterpret_cast<const float4*>(src);
                    float4 fb = *reinterpret_cast<const float4*>(src + 4);
                    float4 wa = *reinterpret_cast<const float4*>(swg_s + h * 32);
                    float4 wb = *reinterpret_cast<const float4*>(swg_s + h * 32 + 4);
                    sk += fa.x*wa.x + fa.y*wa.y + fa.z*wa.z + fa.w*wa.w;
                    sk += fb.x*wb.x + fb.y*wb.y + fb.z*wb.z + fb.w*wb.w;
                    uint4 hv, lv;
                    hv.x = pack_pair(fa.x, fa.y, lv.x);
                    hv.y = pack_pair(fa.z, fa.w, lv.y);
                    hv.z = pack_pair(fb.x, fb.y, lv.z);
                    hv.w = pack_pair(fb.z, fb.w, lv.w);
                    *reinterpret_cast<uint4*>(dh + h * 64) = hv;
                    *reinterpret_cast<uint4*>(dl + h * 64) = lv;
                }
                skacc[j] += sk;
            }
        }

        CP_WAIT0();        // B(s) landed (only outstanding group)
        __syncthreads();   // A(s) + B(s) visible to all

        // ---- prefetch B(s+1) into other buffer; advance col bases
        if (s + 1 < S) {
            const char* gb = reinterpret_cast<const char*>(g_Bh) + (size_t)(s + 1) * BTILE;
            const unsigned db = sbase + SM_B0 + (buf ^ 1) * BTILE;
            #pragma unroll
            for (int i = 0; i < 3; ++i) {
                int j = tid + i * THREADS;
                if (j < BTILE / 16) CP16(db + j * 16, gb + j * 16);
            }
            CP_COMMIT();
            cid0 = col_ids[(s + 1) * 64];
            cid1 = col_ids[(s + 1) * 64 + 32];
        }

        // ---- 2-term split MMA: D[32x64] per warp
        float d[2][8][4];
        #pragma unroll
        for (int mt = 0; mt < 2; ++mt)
            #pragma unroll
            for (int nt = 0; nt < 8; ++nt)
                { d[mt][nt][0]=0.f; d[mt][nt][1]=0.f; d[mt][nt][2]=0.f; d[mt][nt][3]=0.f; }

        const unsigned bseg = b_base + buf * BTILE;
        #pragma unroll
        for (int kk = 0; kk < 4; ++kk) {
            unsigned ah[2][4], al[2][4];
            #pragma unroll
            for (int mt = 0; mt < 2; ++mt) {
                LDSM_X4(ah[mt][0], ah[mt][1], ah[mt][2], ah[mt][3], a_hi + mt * 2304 + kk * 32);
                LDSM_X4(al[mt][0], al[mt][1], al[mt][2], al[mt][3], a_lo + mt * 2304 + kk * 32);
            }
            #pragma unroll
            for (int ntp = 0; ntp < 4; ++ntp) {
                unsigned bh0, bh1, bh2, bh3;
                LDSM_X4(bh0, bh1, bh2, bh3, bseg + ntp * 2304 + kk * 32);
                #pragma unroll
                for (int mt = 0; mt < 2; ++mt) {
                    MMA_F16(d[mt][2*ntp],   ah[mt][0],ah[mt][1],ah[mt][2],ah[mt][3], bh0, bh1);
                    MMA_F16(d[mt][2*ntp],   al[mt][0],al[mt][1],al[mt][2],al[mt][3], bh0, bh1);
                    MMA_F16(d[mt][2*ntp+1], ah[mt][0],ah[mt][1],ah[mt][2],ah[mt][3], bh2, bh3);
                    MMA_F16(d[mt][2*ntp+1], al[mt][0],al[mt][1],al[mt][2],al[mt][3], bh2, bh3);
                }
            }
        }

        // ---- epilogue: relu(d+b1).W2 (fp32 params, cached), quad reduce
        {
            const float2* bw = g_b1w2 + s * H;
            const int cbase = 2 * (lane & 3);
            #pragma unroll
            for (int mt = 0; mt < 2; ++mt) {
                float p0 = 0.f, p1 = 0.f;
                #pragma unroll
                for (int nt = 0; nt < 8; ++nt) {
                    const float2 bw0 = bw[nt * 8 + cbase];
                    const float2 bw1 = bw[nt * 8 + cbase + 1];
                    p0 += fmaxf(d[mt][nt][0] + bw0.x, 0.f) * bw0.y;
                    p0 += fmaxf(d[mt][nt][1] + bw1.x, 0.f) * bw1.y;
                    p1 += fmaxf(d[mt][nt][2] + bw0.x, 0.f) * bw0.y;
                    p1 += fmaxf(d[mt][nt][3] + bw1.x, 0.f) * bw1.y;
                }
                p0 += __shfl_xor_sync(0xffffffffu, p0, 1);
                p0 += __shfl_xor_sync(0xffffffffu, p0, 2);
                p1 += __shfl_xor_sync(0xffffffffu, p1, 1);
                p1 += __shfl_xor_sync(0xffffffffu, p1, 2);
                rowacc[mt][0] += p0;
                rowacc[mt][1] += p1;
            }
        }
    }

    // ---- finalize: reduce skip partials over the 4 lanes of each row
    {
        float* skp = reinterpret_cast<float*>(smem + SM_SKP);
        #pragma unroll
        for (int j = 0; j < 4; ++j) {
            float v = skacc[j];
            v += __shfl_xor_sync(0xffffffffu, v, 1);
            v += __shfl_xor_sync(0xffffffffu, v, 2);
            if (gc2 == 0) skp[j * 64 + gr0] = v;
        }
    }
    __syncthreads();

    if ((lane & 3) == 0) {
        const float* skp = reinterpret_cast<const float*>(smem + SM_SKP);
        const float extras = g_extras;
        #pragma unroll
        for (int mt = 0; mt < 2; ++mt) {
            const int lr = wid * 32 + mt * 16 + (lane >> 2);
            float v0 = rowacc[mt][0] + extras + skp[lr];
            float v1 = rowacc[mt][1] + extras + skp[lr + 8];
            out[rowbase + lr]     = fminf(fmaxf(v0, -20.0f), 20.0f);
            out[rowbase + lr + 8] = fminf(fmaxf(v1, -20.0f), 20.0f);
        }
    }
}

// ------------------------------------------------------------------ launch
extern "C" void kernel_launch(void* const* d_in, const int* in_sizes, int n_in,
                              void* d_out, int out_size)
{
    const float* x       = (const float*)d_in[0];
    const float* skip_w  = (const float*)d_in[1];
    const float* skip_b  = (const float*)d_in[2];
    const float* W1      = (const float*)d_in[3];
    const float* b1      = (const float*)d_in[4];
    const float* W2      = (const float*)d_in[5];
    const float* b2      = (const float*)d_in[6];
    const int*   col_ids = (const int*)  d_in[7];
    float* out = (float*)d_out;

    static bool attr_set = false;
    if (!attr_set) {
        cudaFuncSetAttribute(hybrid_main,
                             cudaFuncAttributeMaxDynamicSharedMemorySize, SM_TOTAL);
        attr_set = true;
    }

    const int prep_items = S * 64 * 72 + S * H + S * 64 + 1;
    prep_all<<<(prep_items + 255) / 256, 256>>>(W1, skip_w, skip_b, b1, W2, b2, col_ids);

    const int nrows = in_sizes[0] / D;   // 65536
    const int grid  = nrows / MROWS;     // 256
    hybrid_main<<<grid, THREADS, SM_TOTAL>>>(x, col_ids, out);
}

// round 10
// speedup vs baseline: 2.1954x; 1.3317x over previous
#include <cuda_runtime.h>
#include <cuda_fp16.h>
#include <cstdint>

// Problem constants
#define D 512
#define S 32
#define H 64
#define MROWS 256           // rows per CTA
#define THREADS 256         // 8 warps, warp = 32 rows x 64 n (MMA phase)
#define ASTRIDE 144         // bytes per A row (64 fp16 + pad) -> conflict-free ldmatrix
#define BSTRIDE 144         // bytes per B n-row (64 fp16 k + pad)
#define BTILE (64*BSTRIDE)  // 9216 B (fp16 W tile)

// smem byte offsets
#define SM_A   0
#define SM_B0  (SM_A + MROWS*ASTRIDE)     // 36864 (+buf*BTILE, double buffered)
#define SM_SKP (SM_B0 + 2*BTILE)          // 55296 (256 floats)
#define SM_TOTAL (SM_SKP + MROWS*4)       // 56320

// W1 pre-rounded fp16, n-major: [s][n=64][k=72pad]
__device__ __half  g_Bh[S * 64 * 72];
__device__ float2  g_b1w2[S * H];
__device__ float   g_swg[S * 64];   // skip_w[col_ids]/4
__device__ float   g_extras;        // skip_b + sum(b2)

// ------------------------------------------------------------------ helpers
__device__ __forceinline__ unsigned smem_u32(const void* p) {
    return (unsigned)__cvta_generic_to_shared(p);
}

__device__ __forceinline__ unsigned pack_h2(float a, float b) {
    __half2 h = __floats2half2_rn(a, b);
    return *reinterpret_cast<unsigned*>(&h);
}

#define LDSM_X4(r0,r1,r2,r3,addr) \
    asm volatile("ldmatrix.sync.aligned.m8n8.x4.shared.b16 {%0,%1,%2,%3}, [%4];" \
        : "=r"(r0),"=r"(r1),"=r"(r2),"=r"(r3) : "r"(addr))

#define MMA_F16(d,a0,a1,a2,a3,b0,b1) \
    asm volatile("mma.sync.aligned.m16n8k16.row.col.f32.f16.f16.f32 " \
        "{%0,%1,%2,%3}, {%4,%5,%6,%7}, {%8,%9}, {%0,%1,%2,%3};" \
        : "+f"((d)[0]),"+f"((d)[1]),"+f"((d)[2]),"+f"((d)[3]) \
        : "r"(a0),"r"(a1),"r"(a2),"r"(a3),"r"(b0),"r"(b1))

#define CP16(dst, src) \
    asm volatile("cp.async.cg.shared.global [%0], [%1], 16;" :: "r"(dst), "l"(src))
#define CP_COMMIT() asm volatile("cp.async.commit_group;")
#define CP_WAIT0()  asm volatile("cp.async.wait_group 0;")

// ------------------------------------------------------------------ fused prep
__global__ void prep_all(const float* __restrict__ W1,
                         const float* __restrict__ skip_w,
                         const float* __restrict__ skip_b,
                         const float* __restrict__ b1,
                         const float* __restrict__ W2,
                         const float* __restrict__ b2,
                         const int*   __restrict__ col_ids)
{
    int idx = blockIdx.x * blockDim.x + threadIdx.x;
    if (idx < S * 64 * 72) {
        int s = idx / (64 * 72);
        int rem = idx % (64 * 72);
        int n = rem / 72;           // h index (B row, n-major)
        int k = rem % 72;           // c index
        float v = (k < 64) ? W1[(size_t)s * 4096 + (size_t)k * 64 + n] : 0.f;
        g_Bh[idx] = __float2half_rn(v);
        return;
    }
    int r = idx - S * 64 * 72;
    if (r < S * H) { g_b1w2[r] = make_float2(b1[r], W2[r]); return; }
    r -= S * H;
    if (r < S * 64) { g_swg[r] = skip_w[col_ids[r]] * 0.25f; return; }
    if (r == S * 64) {
        float e = skip_b[0];
        for (int s = 0; s < S; ++s) e += b2[s];
        g_extras = e;
    }
}

// ------------------------------------------------------------------ main
__global__ void __launch_bounds__(THREADS, 2)
hybrid_main(const float* __restrict__ x,
            const int*   __restrict__ col_ids,
            float* __restrict__ out)
{
    extern __shared__ char smem[];
    const unsigned sbase = smem_u32(smem);
    const int tid  = threadIdx.x;
    const int lane = tid & 31;
    const int wid  = tid >> 5;
    const int rowbase = blockIdx.x * MROWS;

    // A ldmatrix lane address (mt tile offset = 16*ASTRIDE = 2304)
    const int a_row = wid * 32 + ((lane >> 3) & 1) * 8 + (lane & 7);
    const unsigned a_base = sbase + SM_A + a_row * ASTRIDE + (lane >> 4) * 16;

    // B ldmatrix (non-trans x4, n-major rows):
    // group g=lane>>3: n = (g>>1)*8 + (lane&7), koff = (g&1)*16
    const int bg = lane >> 3;
    const unsigned b_base = sbase + SM_B0
        + (((bg >> 1) * 8) + (lane & 7)) * BSTRIDE + (bg & 1) * 16;

    // gather identity: warp covers 8 rows x 4 lanes (32B each, coalesced)
    const int gr0 = wid * 8 + (lane >> 2);   // row within each 64-row block
    const int gc2 = lane & 3;                // 32B unit within the 128B half
    const float* xb = x + (size_t)rowbase * D + gc2 * 8;

    // ---------------- prologue: cp.async B(0) ----------------
    {
        const char* gb = reinterpret_cast<const char*>(g_Bh);
        const unsigned db = sbase + SM_B0;
        #pragma unroll
        for (int i = 0; i < 3; ++i) {
            int j = tid + i * THREADS;
            if (j < BTILE / 16) CP16(db + j * 16, gb + j * 16);
        }
        CP_COMMIT();
    }

    float rowacc[2][2] = {{0.f, 0.f}, {0.f, 0.f}};
    float skacc[4] = {0.f, 0.f, 0.f, 0.f};
    int cid0 = col_ids[0];
    int cid1 = col_ids[32];

    for (int s = 0; s < S; ++s) {
        const int buf = s & 1;
        __syncthreads();   // A(s-1) fully consumed by all warps

        // ---- coalesced gather + fp16 convert + fp32 skip partials
        {
            const float* swg_s = g_swg + s * 64 + gc2 * 8;
            #pragma unroll
            for (int j = 0; j < 4; ++j) {
                const int row = j * 64 + gr0;
                const float* xr = xb + (size_t)row * D;
                char* dst = smem + SM_A + row * ASTRIDE + gc2 * 16;
                float sk = 0.f;
                #pragma unroll
                for (int h = 0; h < 2; ++h) {
                    const float* src = xr + (h ? cid1 : cid0);
                    float4 fa = *reinterpret_cast<const float4*>(src);
                    float4 fb = *reinterpret_cast<const float4*>(src + 4);
                    float4 wa = *reinterpret_cast<const float4*>(swg_s + h * 32);
                    float4 wb = *reinterpret_cast<const float4*>(swg_s + h * 32 + 4);
                    sk += fa.x*wa.x + fa.y*wa.y + fa.z*wa.z + fa.w*wa.w;
                    sk += fb.x*wb.x + fb.y*wb.y + fb.z*wb.z + fb.w*wb.w;
                    uint4 hv;
                    hv.x = pack_h2(fa.x, fa.y);
                    hv.y = pack_h2(fa.z, fa.w);
                    hv.z = pack_h2(fb.x, fb.y);
                    hv.w = pack_h2(fb.z, fb.w);
                    *reinterpret_cast<uint4*>(dst + h * 64) = hv;
                }
                skacc[j] += sk;
            }
        }

        CP_WAIT0();        // B(s) landed (only outstanding group)
        __syncthreads();   // A(s) + B(s) visible to all

        // ---- prefetch B(s+1) into other buffer; advance col bases
        if (s + 1 < S) {
            const char* gb = reinterpret_cast<const char*>(g_Bh) + (size_t)(s + 1) * BTILE;
            const unsigned db = sbase + SM_B0 + (buf ^ 1) * BTILE;
            #pragma unroll
            for (int i = 0; i < 3; ++i) {
                int j = tid + i * THREADS;
                if (j < BTILE / 16) CP16(db + j * 16, gb + j * 16);
            }
            CP_COMMIT();
            cid0 = col_ids[(s + 1) * 64];
            cid1 = col_ids[(s + 1) * 64 + 32];
        }

        // ---- single-term fp16 MMA: D[32x64] per warp
        float d[2][8][4];
        #pragma unroll
        for (int mt = 0; mt < 2; ++mt)
            #pragma unroll
            for (int nt = 0; nt < 8; ++nt)
                { d[mt][nt][0]=0.f; d[mt][nt][1]=0.f; d[mt][nt][2]=0.f; d[mt][nt][3]=0.f; }

        const unsigned bseg = b_base + buf * BTILE;
        #pragma unroll
        for (int kk = 0; kk < 4; ++kk) {
            unsigned ah[2][4];
            #pragma unroll
            for (int mt = 0; mt < 2; ++mt)
                LDSM_X4(ah[mt][0], ah[mt][1], ah[mt][2], ah[mt][3], a_base + mt * 2304 + kk * 32);
            #pragma unroll
            for (int ntp = 0; ntp < 4; ++ntp) {
                unsigned bh0, bh1, bh2, bh3;
                LDSM_X4(bh0, bh1, bh2, bh3, bseg + ntp * 2304 + kk * 32);
                #pragma unroll
                for (int mt = 0; mt < 2; ++mt) {
                    MMA_F16(d[mt][2*ntp],   ah[mt][0],ah[mt][1],ah[mt][2],ah[mt][3], bh0, bh1);
                    MMA_F16(d[mt][2*ntp+1], ah[mt][0],ah[mt][1],ah[mt][2],ah[mt][3], bh2, bh3);
                }
            }
        }

        // ---- epilogue: relu(d+b1).W2 (fp32 params, cached), quad reduce
        {
            const float2* bw = g_b1w2 + s * H;
            const int cbase = 2 * (lane & 3);
            #pragma unroll
            for (int mt = 0; mt < 2; ++mt) {
                float p0 = 0.f, p1 = 0.f;
                #pragma unroll
                for (int nt = 0; nt < 8; ++nt) {
                    const float2 bw0 = bw[nt * 8 + cbase];
                    const float2 bw1 = bw[nt * 8 + cbase + 1];
                    p0 += fmaxf(d[mt][nt][0] + bw0.x, 0.f) * bw0.y;
                    p0 += fmaxf(d[mt][nt][1] + bw1.x, 0.f) * bw1.y;
                    p1 += fmaxf(d[mt][nt][2] + bw0.x, 0.f) * bw0.y;
                    p1 += fmaxf(d[mt][nt][3] + bw1.x, 0.f) * bw1.y;
                }
                p0 += __shfl_xor_sync(0xffffffffu, p0, 1);
                p0 += __shfl_xor_sync(0xffffffffu, p0, 2);
                p1 += __shfl_xor_sync(0xffffffffu, p1, 1);
                p1 += __shfl_xor_sync(0xffffffffu, p1, 2);
                rowacc[mt][0] += p0;
                rowacc[mt][1] += p1;
            }
        }
    }

    // ---- finalize: reduce skip partials over the 4 lanes of each row
    {
        float* skp = reinterpret_cast<float*>(smem + SM_SKP);
        #pragma unroll
        for (int j = 0; j < 4; ++j) {
            float v = skacc[j];
            v += __shfl_xor_sync(0xffffffffu, v, 1);
            v += __shfl_xor_sync(0xffffffffu, v, 2);
            if (gc2 == 0) skp[j * 64 + gr0] = v;
        }
    }
    __syncthreads();

    if ((lane & 3) == 0) {
        const float* skp = reinterpret_cast<const float*>(smem + SM_SKP);
        const float extras = g_extras;
        #pragma unroll
        for (int mt = 0; mt < 2; ++mt) {
            const int lr = wid * 32 + mt * 16 + (lane >> 2);
            float v0 = rowacc[mt][0] + extras + skp[lr];
            float v1 = rowacc[mt][1] + extras + skp[lr + 8];
            out[rowbase + lr]     = fminf(fmaxf(v0, -20.0f), 20.0f);
            out[rowbase + lr + 8] = fminf(fmaxf(v1, -20.0f), 20.0f);
        }
    }
}

// ------------------------------------------------------------------ launch
extern "C" void kernel_launch(void* const* d_in, const int* in_sizes, int n_in,
                              void* d_out, int out_size)
{
    const float* x       = (const float*)d_in[0];
    const float* skip_w  = (const float*)d_in[1];
    const float* skip_b  = (const float*)d_in[2];
    const float* W1      = (const float*)d_in[3];
    const float* b1      = (const float*)d_in[4];
    const float* W2      = (const float*)d_in[5];
    const float* b2      = (const float*)d_in[6];
    const int*   col_ids = (const int*)  d_in[7];
    float* out = (float*)d_out;

    static bool attr_set = false;
    if (!attr_set) {
        cudaFuncSetAttribute(hybrid_main,
                             cudaFuncAttributeMaxDynamicSharedMemorySize, SM_TOTAL);
        attr_set = true;
    }

    const int prep_items = S * 64 * 72 + S * H + S * 64 + 1;
    prep_all<<<(prep_items + 255) / 256, 256>>>(W1, skip_w, skip_b, b1, W2, b2, col_ids);

    const int nrows = in_sizes[0] / D;   // 65536
    const int grid  = nrows / MROWS;     // 256
    hybrid_main<<<grid, THREADS, SM_TOTAL>>>(x, col_ids, out);
}

// round 11
// speedup vs baseline: 3.3747x; 1.5372x over previous
#include <cuda_runtime.h>
#include <cuda_fp16.h>
#include <cstdint>

// Problem constants
#define D 512
#define S 32
#define H 64
#define MROWS 256           // rows per CTA
#define THREADS 256         // 8 warps, warp = 32 rows x 64 n (MMA phase)
#define BSTRIDE 144         // bytes per B n-row (64 fp16 k + pad)
#define BTILE (64*BSTRIDE)  // 9216 B (fp16 W tile)
#define SLOT_BYTES (MROWS*64)   // 16 KB: 256 rows x 32 fp16 (64B, XOR-swizzled chunks)

// smem byte offsets
#define SM_A    0                          // 4 group slots
#define SM_B0   (SM_A + 4*SLOT_BYTES)      // 65536 (+buf*BTILE, double buffered)
#define SM_SKP  (SM_B0 + 2*BTILE)          // 83968 (256 floats)
#define SM_TOTAL (SM_SKP + MROWS*4)        // 84992 -> 2 CTAs/SM

// W1 pre-rounded fp16, n-major: [s][n=64][k=72pad]
__device__ __half  g_Bh[S * 64 * 72];
__device__ float2  g_b1w2[S * H];
__device__ float   g_extras;        // skip_b + sum(b2)

// ------------------------------------------------------------------ helpers
__device__ __forceinline__ unsigned smem_u32(const void* p) {
    return (unsigned)__cvta_generic_to_shared(p);
}

__device__ __forceinline__ unsigned pack_h2(float a, float b) {
    __half2 h = __floats2half2_rn(a, b);
    return *reinterpret_cast<unsigned*>(&h);
}

#define LDSM_X4(r0,r1,r2,r3,addr) \
    asm volatile("ldmatrix.sync.aligned.m8n8.x4.shared.b16 {%0,%1,%2,%3}, [%4];" \
        : "=r"(r0),"=r"(r1),"=r"(r2),"=r"(r3) : "r"(addr))

#define MMA_F16(d,a0,a1,a2,a3,b0,b1) \
    asm volatile("mma.sync.aligned.m16n8k16.row.col.f32.f16.f16.f32 " \
        "{%0,%1,%2,%3}, {%4,%5,%6,%7}, {%8,%9}, {%0,%1,%2,%3};" \
        : "+f"((d)[0]),"+f"((d)[1]),"+f"((d)[2]),"+f"((d)[3]) \
        : "r"(a0),"r"(a1),"r"(a2),"r"(a3),"r"(b0),"r"(b1))

#define CP16(dst, src) \
    asm volatile("cp.async.cg.shared.global [%0], [%1], 16;" :: "r"(dst), "l"(src))
#define CP_COMMIT() asm volatile("cp.async.commit_group;")
#define CP_WAIT0()  asm volatile("cp.async.wait_group 0;")

// ------------------------------------------------------------------ fused prep
__global__ void prep_all(const float* __restrict__ W1,
                         const float* __restrict__ skip_b,
                         const float* __restrict__ b1,
                         const float* __restrict__ W2,
                         const float* __restrict__ b2)
{
    int idx = blockIdx.x * blockDim.x + threadIdx.x;
    if (idx < S * 64 * 72) {
        int s = idx / (64 * 72);
        int rem = idx % (64 * 72);
        int n = rem / 72;           // h index (B row, n-major)
        int k = rem % 72;           // c index
        float v = (k < 64) ? W1[(size_t)s * 4096 + (size_t)k * 64 + n] : 0.f;
        g_Bh[idx] = __float2half_rn(v);
        return;
    }
    int r = idx - S * 64 * 72;
    if (r < S * H) { g_b1w2[r] = make_float2(b1[r], W2[r]); return; }
    r -= S * H;
    if (r == 0) {
        float e = skip_b[0];
        for (int s = 0; s < S; ++s) e += b2[s];
        g_extras = e;
    }
}

// ------------------------------------------------------------------ main
// Position order p=0..31: seg = (p&1)*16 + (p>>1).
// seg groups: ga = p>>1, gb = (ga + 1 + (p&1)) & 15. Slot of group g = g&3.
// Group loads: prologue g0,g1; at each even p: group (p>>1 + 2)&15
// (p=28,30 reload g0,g1 -> no skip-dot recompute).
__global__ void __launch_bounds__(THREADS, 2)
hybrid_main(const float* __restrict__ x,
            const float* __restrict__ skip_w,
            float* __restrict__ out)
{
    extern __shared__ char smem[];
    const unsigned sbase = smem_u32(smem);
    const int tid  = threadIdx.x;
    const int lane = tid & 31;
    const int wid  = tid >> 5;
    const int rowbase = blockIdx.x * MROWS;

    // A ldmatrix lane offsets within a slot (XOR-swizzled 16B chunks)
    const int row_l = (lane & 7) + ((lane >> 3) & 1) * 8;
    const int swz   = (row_l >> 1) & 3;
    const unsigned aoff0 = row_l * 64 + (((0 + (lane >> 4)) ^ swz) * 16);   // kl=0: chunk 0/1
    const unsigned aoff1 = row_l * 64 + (((2 + (lane >> 4)) ^ swz) * 16);   // kl=1: chunk 2/3
    const unsigned awarp = wid * 2048;                                      // 32 rows * 64 B

    // B ldmatrix (non-trans x4, n-major rows)
    const int bg = lane >> 3;
    const unsigned b_base = sbase + SM_B0
        + (((bg >> 1) * 8) + (lane & 7)) * BSTRIDE + (bg & 1) * 16;

    // gather identity: instr covers 4 rows, 8 lanes = one full 128B line per row
    const int g_r = wid * 4 + (lane >> 3);   // row within a 32-row round
    const int g_c = lane & 7;                // 16B piece of the 128B fp32 line
    const unsigned csw = (((g_c >> 1) ^ ((g_r >> 1) & 3)) * 16) + (g_c & 1) * 8;

    float skacc[8] = {0.f,0.f,0.f,0.f,0.f,0.f,0.f,0.f};

    // group loader (inlined via lambda-like macro using locals)
    auto load_group = [&](int g, bool do_skip) {
        char* slot = smem + SM_A + (g & 3) * SLOT_BYTES;
        const float* xg = x + (size_t)rowbase * D + g * 32 + g_c * 4;
        float4 w = make_float4(0.f, 0.f, 0.f, 0.f);
        if (do_skip) w = *reinterpret_cast<const float4*>(skip_w + g * 32 + g_c * 4);
        #pragma unroll
        for (int it = 0; it < 8; ++it) {
            const int r = it * 32 + g_r;
            float4 v = *reinterpret_cast<const float4*>(xg + (size_t)r * D);
            if (do_skip)
                skacc[it] += v.x * w.x + v.y * w.y + v.z * w.z + v.w * w.w;
            uint2 hv = make_uint2(pack_h2(v.x, v.y), pack_h2(v.z, v.w));
            *reinterpret_cast<uint2*>(slot + r * 64 + csw) = hv;
        }
    };

    // ---------------- prologue: B(seg 0) + groups 0,1 ----------------
    {
        const char* gb0 = reinterpret_cast<const char*>(g_Bh);
        const unsigned db = sbase + SM_B0;
        #pragma unroll
        for (int i = 0; i < 3; ++i) {
            int j = tid + i * THREADS;
            if (j < BTILE / 16) CP16(db + j * 16, gb0 + j * 16);
        }
        CP_COMMIT();
    }
    load_group(0, true);
    load_group(1, true);

    float rowacc[2][2] = {{0.f, 0.f}, {0.f, 0.f}};

    for (int p = 0; p < 32; ++p) {
        const int ga  = p >> 1;
        const int odd = p & 1;
        const int gb_grp = (ga + 1 + odd) & 15;
        const int seg = odd * 16 + ga;
        const int buf = p & 1;

        __syncthreads();   // previous position fully consumed

        // ---- load next group (even positions only); reloads skip the dot
        if (!odd) load_group((ga + 2) & 15, p <= 26);

        CP_WAIT0();        // B(seg) landed
        __syncthreads();   // A slots + B(seg) visible to all

        // ---- prefetch B for next position
        if (p + 1 < 32) {
            const int nseg = ((p + 1) & 1) * 16 + ((p + 1) >> 1);
            const char* gbp = reinterpret_cast<const char*>(g_Bh) + (size_t)nseg * BTILE;
            const unsigned db = sbase + SM_B0 + (buf ^ 1) * BTILE;
            #pragma unroll
            for (int i = 0; i < 3; ++i) {
                int j = tid + i * THREADS;
                if (j < BTILE / 16) CP16(db + j * 16, gbp + j * 16);
            }
            CP_COMMIT();
        }

        // ---- single-term fp16 MMA: D[32x64] per warp
        float d[2][8][4];
        #pragma unroll
        for (int mt = 0; mt < 2; ++mt)
            #pragma unroll
            for (int nt = 0; nt < 8; ++nt)
                { d[mt][nt][0]=0.f; d[mt][nt][1]=0.f; d[mt][nt][2]=0.f; d[mt][nt][3]=0.f; }

        const unsigned slota = sbase + SM_A + (ga & 3) * SLOT_BYTES + awarp;
        const unsigned slotb = sbase + SM_A + (gb_grp & 3) * SLOT_BYTES + awarp;
        const unsigned bseg = b_base + buf * BTILE;
        #pragma unroll
        for (int kk = 0; kk < 4; ++kk) {
            const unsigned abase = ((kk < 2) ? slota : slotb) + ((kk & 1) ? aoff1 : aoff0);
            unsigned ah[2][4];
            #pragma unroll
            for (int mt = 0; mt < 2; ++mt)
                LDSM_X4(ah[mt][0], ah[mt][1], ah[mt][2], ah[mt][3], abase + mt * 1024);
            #pragma unroll
            for (int ntp = 0; ntp < 4; ++ntp) {
                unsigned bh0, bh1, bh2, bh3;
                LDSM_X4(bh0, bh1, bh2, bh3, bseg + ntp * 2304 + kk * 32);
                #pragma unroll
                for (int mt = 0; mt < 2; ++mt) {
                    MMA_F16(d[mt][2*ntp],   ah[mt][0],ah[mt][1],ah[mt][2],ah[mt][3], bh0, bh1);
                    MMA_F16(d[mt][2*ntp+1], ah[mt][0],ah[mt][1],ah[mt][2],ah[mt][3], bh2, bh3);
                }
            }
        }

        // ---- epilogue: relu(d+b1).W2, quad reduce
        {
            const float2* bw = g_b1w2 + seg * H;
            const int cbase = 2 * (lane & 3);
            #pragma unroll
            for (int mt = 0; mt < 2; ++mt) {
                float p0 = 0.f, p1 = 0.f;
                #pragma unroll
                for (int nt = 0; nt < 8; ++nt) {
                    const float2 bw0 = bw[nt * 8 + cbase];
                    const float2 bw1 = bw[nt * 8 + cbase + 1];
                    p0 += fmaxf(d[mt][nt][0] + bw0.x, 0.f) * bw0.y;
                    p0 += fmaxf(d[mt][nt][1] + bw1.x, 0.f) * bw1.y;
                    p1 += fmaxf(d[mt][nt][2] + bw0.x, 0.f) * bw0.y;
                    p1 += fmaxf(d[mt][nt][3] + bw1.x, 0.f) * bw1.y;
                }
                p0 += __shfl_xor_sync(0xffffffffu, p0, 1);
                p0 += __shfl_xor_sync(0xffffffffu, p0, 2);
                p1 += __shfl_xor_sync(0xffffffffu, p1, 1);
                p1 += __shfl_xor_sync(0xffffffffu, p1, 2);
                rowacc[mt][0] += p0;
                rowacc[mt][1] += p1;
            }
        }
    }

    // ---- finalize: reduce skip partials over the 8 lanes sharing each row
    {
        float* skp = reinterpret_cast<float*>(smem + SM_SKP);
        #pragma unroll
        for (int it = 0; it < 8; ++it) {
            float v = skacc[it];
            v += __shfl_xor_sync(0xffffffffu, v, 1);
            v += __shfl_xor_sync(0xffffffffu, v, 2);
            v += __shfl_xor_sync(0xffffffffu, v, 4);
            if (g_c == 0) skp[it * 32 + g_r] = v;
        }
    }
    __syncthreads();

    if ((lane & 3) == 0) {
        const float* skp = reinterpret_cast<const float*>(smem + SM_SKP);
        const float extras = g_extras;
        #pragma unroll
        for (int mt = 0; mt < 2; ++mt) {
            const int lr = wid * 32 + mt * 16 + (lane >> 2);
            float v0 = rowacc[mt][0] + extras + skp[lr];
            float v1 = rowacc[mt][1] + extras + skp[lr + 8];
            out[rowbase + lr]     = fminf(fmaxf(v0, -20.0f), 20.0f);
            out[rowbase + lr + 8] = fminf(fmaxf(v1, -20.0f), 20.0f);
        }
    }
}

// ------------------------------------------------------------------ launch
extern "C" void kernel_launch(void* const* d_in, const int* in_sizes, int n_in,
                              void* d_out, int out_size)
{
    const float* x       = (const float*)d_in[0];
    const float* skip_w  = (const float*)d_in[1];
    const float* skip_b  = (const float*)d_in[2];
    const float* W1      = (const float*)d_in[3];
    const float* b1      = (const float*)d_in[4];
    const float* W2      = (const float*)d_in[5];
    const float* b2      = (const float*)d_in[6];
    float* out = (float*)d_out;

    static bool attr_set = false;
    if (!attr_set) {
        cudaFuncSetAttribute(hybrid_main,
                             cudaFuncAttributeMaxDynamicSharedMemorySize, SM_TOTAL);
        attr_set = true;
    }

    const int prep_items = S * 64 * 72 + S * H + 1;
    prep_all<<<(prep_items + 255) / 256, 256>>>(W1, skip_b, b1, W2, b2);

    const int nrows = in_sizes[0] / D;   // 65536
    const int grid  = nrows / MROWS;     // 256
    hybrid_main<<<grid, THREADS, SM_TOTAL>>>(x, skip_w, out);
}

// round 12
// speedup vs baseline: 3.5859x; 1.0626x over previous
#include <cuda_runtime.h>
#include <cuda_fp16.h>
#include <cstdint>

// Problem constants
#define D 512
#define S 32
#define H 64
#define MROWS 256           // rows per CTA
#define THREADS 256         // 8 warps, warp = 32 rows x 64 n (MMA phase)
#define BSTRIDE 144         // bytes per B n-row (64 fp16 k + pad)
#define BTILE (64*BSTRIDE)  // 9216 B (fp16 W tile)
#define SLOT_BYTES (MROWS*64)   // 16 KB: 256 rows x 32 fp16

// smem byte offsets
#define SM_A    0                          // 4 group slots (ring)
#define SM_B0   (SM_A + 4*SLOT_BYTES)      // 65536 (+buf*BTILE)
#define SM_SKP  (SM_B0 + 2*BTILE)          // 83968 (256 floats)
#define SM_TOTAL (SM_SKP + MROWS*4)        // 84992 -> 2 CTAs/SM

// W1 pre-rounded fp16, n-major: [s][n=64][k=72pad]
__device__ __half  g_Bh[S * 64 * 72];
__device__ float2  g_b1w2[S * H];
__device__ float   g_extras;        // skip_b + sum(b2)

// ------------------------------------------------------------------ helpers
__device__ __forceinline__ unsigned smem_u32(const void* p) {
    return (unsigned)__cvta_generic_to_shared(p);
}
__device__ __forceinline__ unsigned pack_h2(float a, float b) {
    __half2 h = __floats2half2_rn(a, b);
    return *reinterpret_cast<unsigned*>(&h);
}

#define LDSM_X4(r0,r1,r2,r3,addr) \
    asm volatile("ldmatrix.sync.aligned.m8n8.x4.shared.b16 {%0,%1,%2,%3}, [%4];" \
        : "=r"(r0),"=r"(r1),"=r"(r2),"=r"(r3) : "r"(addr))

#define MMA_F16(d,a0,a1,a2,a3,b0,b1) \
    asm volatile("mma.sync.aligned.m16n8k16.row.col.f32.f16.f16.f32 " \
        "{%0,%1,%2,%3}, {%4,%5,%6,%7}, {%8,%9}, {%0,%1,%2,%3};" \
        : "+f"((d)[0]),"+f"((d)[1]),"+f"((d)[2]),"+f"((d)[3]) \
        : "r"(a0),"r"(a1),"r"(a2),"r"(a3),"r"(b0),"r"(b1))

#define CP16(dst, src) \
    asm volatile("cp.async.cg.shared.global [%0], [%1], 16;" :: "r"(dst), "l"(src))
#define CP_COMMIT() asm volatile("cp.async.commit_group;")
#define CP_WAIT0()  asm volatile("cp.async.wait_group 0;")

// ------------------------------------------------------------------ fused prep
__global__ void prep_all(const float* __restrict__ W1,
                         const float* __restrict__ skip_b,
                         const float* __restrict__ b1,
                         const float* __restrict__ W2,
                         const float* __restrict__ b2)
{
    int idx = blockIdx.x * blockDim.x + threadIdx.x;
    if (idx < S * 64 * 72) {
        int s = idx / (64 * 72);
        int rem = idx % (64 * 72);
        int n = rem / 72;
        int k = rem % 72;
        float v = (k < 64) ? W1[(size_t)s * 4096 + (size_t)k * 64 + n] : 0.f;
        g_Bh[idx] = __float2half_rn(v);
        return;
    }
    int r = idx - S * 64 * 72;
    if (r < S * H) { g_b1w2[r] = make_float2(b1[r], W2[r]); return; }
    r -= S * H;
    if (r == 0) {
        float e = skip_b[0];
        for (int s = 0; s < S; ++s) e += b2[s];
        g_extras = e;
    }
}

// ------------------------------------------------------------------ main
// Position p=0..31: seg = (p&1)*16 + (p>>1); groups ga=p>>1, gb=(ga+1+(p&1))&15.
// Slot of group g = g&3. Prologue: full groups 0,1,2. Position pair (2pp,2pp+1)
// loads halves 0,1 of group (pp+3)&15 (skip-dot iff pp<=12; nothing at pp=15).
// ONE __syncthreads per position (write->read gap >= 2 positions verified).
__global__ void __launch_bounds__(THREADS, 2)
hybrid_main(const float* __restrict__ x,
            const float* __restrict__ skip_w,
            float* __restrict__ out)
{
    extern __shared__ char smem[];
    const unsigned sbase = smem_u32(smem);
    const int tid  = threadIdx.x;
    const int lane = tid & 31;
    const int wid  = tid >> 5;
    const int rowbase = blockIdx.x * MROWS;

    // A ldmatrix lane offsets within a slot (XOR-swizzled 16B chunks)
    const int row_l = (lane & 7) + ((lane >> 3) & 1) * 8;
    const int swz   = (row_l >> 1) & 3;
    const unsigned aoff0 = row_l * 64 + (((0 + (lane >> 4)) ^ swz) * 16);
    const unsigned aoff1 = row_l * 64 + (((2 + (lane >> 4)) ^ swz) * 16);
    const unsigned awarp = wid * 2048;

    // B ldmatrix (non-trans x4, n-major rows)
    const int bg = lane >> 3;
    const unsigned b_base = sbase + SM_B0
        + (((bg >> 1) * 8) + (lane & 7)) * BSTRIDE + (bg & 1) * 16;

    // gather identity: 8 lanes cover one full 128B line per row
    const int g_r = wid * 4 + (lane >> 3);
    const int g_c = lane & 7;
    const unsigned csw = (((g_c >> 1) ^ ((g_r >> 1) & 3)) * 16) + (g_c & 1) * 8;

    float skacc[8] = {0.f,0.f,0.f,0.f,0.f,0.f,0.f,0.f};
    float rowacc[2][2] = {{0.f, 0.f}, {0.f, 0.f}};

    // B stage helper
    auto stage_B = [&](int seg, int buf) {
        const char* gbp = reinterpret_cast<const char*>(g_Bh) + (size_t)seg * BTILE;
        const unsigned db = sbase + SM_B0 + buf * BTILE;
        #pragma unroll
        for (int i = 0; i < 3; ++i) {
            int j = tid + i * THREADS;
            if (j < BTILE / 16) CP16(db + j * 16, gbp + j * 16);
        }
        CP_COMMIT();
    };

    // ---------------- prologue: B(seg 0) + full groups 0,1,2 ----------------
    stage_B(0, 0);
    #pragma unroll
    for (int g = 0; g < 3; ++g) {
        char* slot = smem + SM_A + g * SLOT_BYTES;
        const float* xg = x + (size_t)rowbase * D + g * 32 + g_c * 4;
        float4 w = *reinterpret_cast<const float4*>(skip_w + g * 32 + g_c * 4);
        #pragma unroll
        for (int it = 0; it < 8; ++it) {
            const int r = it * 32 + g_r;
            float4 v = *reinterpret_cast<const float4*>(xg + (size_t)r * D);
            skacc[it] += v.x*w.x + v.y*w.y + v.z*w.z + v.w*w.w;
            uint2 hv = make_uint2(pack_h2(v.x, v.y), pack_h2(v.z, v.w));
            *reinterpret_cast<uint2*>(slot + r * 64 + csw) = hv;
        }
    }

    for (int pp = 0; pp < 16; ++pp) {
        const int gl = (pp + 3) & 15;
        const bool do_load = (pp < 15);
        const bool do_skip = (pp <= 12);
        char* lslot = smem + SM_A + (gl & 3) * SLOT_BYTES;
        const float* lxg = x + (size_t)rowbase * D + gl * 32 + g_c * 4;
        float4 lw = make_float4(0.f,0.f,0.f,0.f);
        if (do_skip) lw = *reinterpret_cast<const float4*>(skip_w + gl * 32 + g_c * 4);

        // =========================== even phase: p=2pp ===========================
        {
            CP_WAIT0();
            __syncthreads();
            stage_B(16 + pp, 1);                      // B for odd phase
            if (do_load) {                             // half 0 of group gl
                #pragma unroll
                for (int i = 0; i < 4; ++i) {
                    const int r = i * 32 + g_r;
                    float4 v = *reinterpret_cast<const float4*>(lxg + (size_t)r * D);
                    if (do_skip) skacc[i] += v.x*lw.x + v.y*lw.y + v.z*lw.z + v.w*lw.w;
                    uint2 hv = make_uint2(pack_h2(v.x, v.y), pack_h2(v.z, v.w));
                    *reinterpret_cast<uint2*>(lslot + r * 64 + csw) = hv;
                }
            }
            // MMA: seg=pp, groups (pp, pp+1), buf 0
            float d[2][8][4];
            #pragma unroll
            for (int mt = 0; mt < 2; ++mt)
                #pragma unroll
                for (int nt = 0; nt < 8; ++nt)
                    { d[mt][nt][0]=0.f; d[mt][nt][1]=0.f; d[mt][nt][2]=0.f; d[mt][nt][3]=0.f; }
            const unsigned slota = sbase + SM_A + (pp & 3) * SLOT_BYTES + awarp;
            const unsigned slotb = sbase + SM_A + ((pp + 1) & 3) * SLOT_BYTES + awarp;
            const unsigned bseg = b_base;
            #pragma unroll
            for (int kk = 0; kk < 4; ++kk) {
                const unsigned abase = ((kk < 2) ? slota : slotb) + ((kk & 1) ? aoff1 : aoff0);
                unsigned ah[2][4];
                #pragma unroll
                for (int mt = 0; mt < 2; ++mt)
                    LDSM_X4(ah[mt][0], ah[mt][1], ah[mt][2], ah[mt][3], abase + mt * 1024);
                #pragma unroll
                for (int ntp = 0; ntp < 4; ++ntp) {
                    unsigned bh0, bh1, bh2, bh3;
                    LDSM_X4(bh0, bh1, bh2, bh3, bseg + ntp * 2304 + kk * 32);
                    #pragma unroll
                    for (int mt = 0; mt < 2; ++mt) {
                        MMA_F16(d[mt][2*ntp],   ah[mt][0],ah[mt][1],ah[mt][2],ah[mt][3], bh0, bh1);
                        MMA_F16(d[mt][2*ntp+1], ah[mt][0],ah[mt][1],ah[mt][2],ah[mt][3], bh2, bh3);
                    }
                }
            }
            const float2* bw = g_b1w2 + pp * H;
            const int cbase = 2 * (lane & 3);
            #pragma unroll
            for (int mt = 0; mt < 2; ++mt) {
                float p0 = 0.f, p1 = 0.f;
                #pragma unroll
                for (int nt = 0; nt < 8; ++nt) {
                    const float2 bw0 = bw[nt * 8 + cbase];
                    const float2 bw1 = bw[nt * 8 + cbase + 1];
                    p0 += fmaxf(d[mt][nt][0] + bw0.x, 0.f) * bw0.y;
                    p0 += fmaxf(d[mt][nt][1] + bw1.x, 0.f) * bw1.y;
                    p1 += fmaxf(d[mt][nt][2] + bw0.x, 0.f) * bw0.y;
                    p1 += fmaxf(d[mt][nt][3] + bw1.x, 0.f) * bw1.y;
                }
                p0 += __shfl_xor_sync(0xffffffffu, p0, 1);
                p0 += __shfl_xor_sync(0xffffffffu, p0, 2);
                p1 += __shfl_xor_sync(0xffffffffu, p1, 1);
                p1 += __shfl_xor_sync(0xffffffffu, p1, 2);
                rowacc[mt][0] += p0;
                rowacc[mt][1] += p1;
            }
        }

        // =========================== odd phase: p=2pp+1 ==========================
        {
            CP_WAIT0();
            __syncthreads();
            if (pp < 15) stage_B(pp + 1, 0);          // B for next even phase
            if (do_load) {                             // half 1 of group gl
                #pragma unroll
                for (int i = 0; i < 4; ++i) {
                    const int r = (4 + i) * 32 + g_r;
                    float4 v = *reinterpret_cast<const float4*>(lxg + (size_t)r * D);
                    if (do_skip) skacc[4 + i] += v.x*lw.x + v.y*lw.y + v.z*lw.z + v.w*lw.w;
                    uint2 hv = make_uint2(pack_h2(v.x, v.y), pack_h2(v.z, v.w));
                    *reinterpret_cast<uint2*>(lslot + r * 64 + csw) = hv;
                }
            }
            // MMA: seg=16+pp, groups (pp, pp+2), buf 1
            float d[2][8][4];
            #pragma unroll
            for (int mt = 0; mt < 2; ++mt)
                #pragma unroll
                for (int nt = 0; nt < 8; ++nt)
                    { d[mt][nt][0]=0.f; d[mt][nt][1]=0.f; d[mt][nt][2]=0.f; d[mt][nt][3]=0.f; }
            const unsigned slota = sbase + SM_A + (pp & 3) * SLOT_BYTES + awarp;
            const unsigned slotb = sbase + SM_A + ((pp + 2) & 3) * SLOT_BYTES + awarp;
            const unsigned bseg = b_base + BTILE;
            #pragma unroll
            for (int kk = 0; kk < 4; ++kk) {
                const unsigned abase = ((kk < 2) ? slota : slotb) + ((kk & 1) ? aoff1 : aoff0);
                unsigned ah[2][4];
                #pragma unroll
                for (int mt = 0; mt < 2; ++mt)
                    LDSM_X4(ah[mt][0], ah[mt][1], ah[mt][2], ah[mt][3], abase + mt * 1024);
                #pragma unroll
                for (int ntp = 0; ntp < 4; ++ntp) {
                    unsigned bh0, bh1, bh2, bh3;
                    LDSM_X4(bh0, bh1, bh2, bh3, bseg + ntp * 2304 + kk * 32);
                    #pragma unroll
                    for (int mt = 0; mt < 2; ++mt) {
                        MMA_F16(d[mt][2*ntp],   ah[mt][0],ah[mt][1],ah[mt][2],ah[mt][3], bh0, bh1);
                        MMA_F16(d[mt][2*ntp+1], ah[mt][0],ah[mt][1],ah[mt][2],ah[mt][3], bh2, bh3);
                    }
                }
            }
            const float2* bw = g_b1w2 + (16 + pp) * H;
            const int cbase = 2 * (lane & 3);
            #pragma unroll
            for (int mt = 0; mt < 2; ++mt) {
                float p0 = 0.f, p1 = 0.f;
                #pragma unroll
                for (int nt = 0; nt < 8; ++nt) {
                    const float2 bw0 = bw[nt * 8 + cbase];
                    const float2 bw1 = bw[nt * 8 + cbase + 1];
                    p0 += fmaxf(d[mt][nt][0] + bw0.x, 0.f) * bw0.y;
                    p0 += fmaxf(d[mt][nt][1] + bw1.x, 0.f) * bw1.y;
                    p1 += fmaxf(d[mt][nt][2] + bw0.x, 0.f) * bw0.y;
                    p1 += fmaxf(d[mt][nt][3] + bw1.x, 0.f) * bw1.y;
                }
                p0 += __shfl_xor_sync(0xffffffffu, p0, 1);
                p0 += __shfl_xor_sync(0xffffffffu, p0, 2);
                p1 += __shfl_xor_sync(0xffffffffu, p1, 1);
                p1 += __shfl_xor_sync(0xffffffffu, p1, 2);
                rowacc[mt][0] += p0;
                rowacc[mt][1] += p1;
            }
        }
    }

    // ---- finalize: reduce skip partials over the 8 lanes sharing each row
    {
        float* skp = reinterpret_cast<float*>(smem + SM_SKP);
        #pragma unroll
        for (int it = 0; it < 8; ++it) {
            float v = skacc[it];
            v += __shfl_xor_sync(0xffffffffu, v, 1);
            v += __shfl_xor_sync(0xffffffffu, v, 2);
            v += __shfl_xor_sync(0xffffffffu, v, 4);
            if (g_c == 0) skp[it * 32 + g_r] = v;
        }
    }
    __syncthreads();

    if ((lane & 3) == 0) {
        const float* skp = reinterpret_cast<const float*>(smem + SM_SKP);
        const float extras = g_extras;
        #pragma unroll
        for (int mt = 0; mt < 2; ++mt) {
            const int lr = wid * 32 + mt * 16 + (lane >> 2);
            float v0 = rowacc[mt][0] + extras + skp[lr];
            float v1 = rowacc[mt][1] + extras + skp[lr + 8];
            out[rowbase + lr]     = fminf(fmaxf(v0, -20.0f), 20.0f);
            out[rowbase + lr + 8] = fminf(fmaxf(v1, -20.0f), 20.0f);
        }
    }
}

// ------------------------------------------------------------------ launch
extern "C" void kernel_launch(void* const* d_in, const int* in_sizes, int n_in,
                              void* d_out, int out_size)
{
    const float* x       = (const float*)d_in[0];
    const float* skip_w  = (const float*)d_in[1];
    const float* skip_b  = (const float*)d_in[2];
    const float* W1      = (const float*)d_in[3];
    const float* b1      = (const float*)d_in[4];
    const float* W2      = (const float*)d_in[5];
    const float* b2      = (const float*)d_in[6];
    float* out = (float*)d_out;

    static bool attr_set = false;
    if (!attr_set) {
        cudaFuncSetAttribute(hybrid_main,
                             cudaFuncAttributeMaxDynamicSharedMemorySize, SM_TOTAL);
        attr_set = true;
    }

    const int prep_items = S * 64 * 72 + S * H + 1;
    prep_all<<<(prep_items + 255) / 256, 256>>>(W1, skip_b, b1, W2, b2);

    const int nrows = in_sizes[0] / D;   // 65536
    const int grid  = nrows / MROWS;     // 256
    hybrid_main<<<grid, THREADS, SM_TOTAL>>>(x, skip_w, out);
}